// round 10
// baseline (speedup 1.0000x reference)
#include <cuda_runtime.h>
#include <cuda_bf16.h>
#include <cstdint>

// Problem shape (fixed by the dataset)
#define B_  32
#define T_  768
#define C_  448
#define E_  256
#define N_  3136          // H*W = 56*56
#define SCALE 0.0625f     // 1/sqrt(E)

#define CHUNK 16
#define GX 196                // pixel-groups per batch: 196*16 = 3136 exact

// -------- device scratch (no allocations allowed) --------
// Zero-initialized statics; re-zeroed each replay (k_residual tail / ticket
// winner) so every graph execution sees clean state.
__device__ float g_a[B_ * C_];       // scale * (q[b]^T k_w)[c]   (atomic acc)
__device__ float g_qkb[B_];          // scale * q[b].k_b          (atomic acc)
__device__ float g_S[B_ * C_];       // attention-weighted channel sums (atomic)
__device__ float g_D[B_];            // exp-sum (atomic)
__device__ float g_pooled[B_ * E_];  // pooled (already /D, +v_b)
__device__ unsigned int g_cnt[B_];   // attn completion tickets per batch

// ============================================================
// Kernel 1: fused q-projection + a-projection.
// grid (8, B_): block computes q[e] for its 32-e slice, then
// contributes partial a[b,c] and qkb[b] via atomicAdd.
// ============================================================
__global__ void __launch_bounds__(256) k_qa(
    const float* __restrict__ text, const float* __restrict__ q_w,
    const float* __restrict__ q_b,  const float* __restrict__ k_w,
    const float* __restrict__ k_b)
{
    int slice = blockIdx.x, b = blockIdx.y;
    int tid = threadIdx.x, warp = tid >> 5, lane = tid & 31;
    __shared__ float txt[T_];
    __shared__ float q_sm[32];

    const float4* tsrc = reinterpret_cast<const float4*>(text + (size_t)b * T_);
    for (int j = tid; j < T_ / 4; j += 256)
        reinterpret_cast<float4*>(txt)[j] = tsrc[j];
    __syncthreads();

    int eBase = slice * 32;
    {
        int e0 = eBase + warp * 4;
        const float4* tt = reinterpret_cast<const float4*>(txt);
        const float4* w0 = reinterpret_cast<const float4*>(q_w + (size_t)(e0 + 0) * T_);
        const float4* w1 = reinterpret_cast<const float4*>(q_w + (size_t)(e0 + 1) * T_);
        const float4* w2 = reinterpret_cast<const float4*>(q_w + (size_t)(e0 + 2) * T_);
        const float4* w3 = reinterpret_cast<const float4*>(q_w + (size_t)(e0 + 3) * T_);
        float a0 = 0.f, a1 = 0.f, a2 = 0.f, a3 = 0.f;
        #pragma unroll
        for (int it = 0; it < 6; ++it) {          // 6*32*4 = 768 exact
            int j = it * 32 + lane;
            float4 y = tt[j];
            float4 x0 = w0[j], x1 = w1[j], x2 = w2[j], x3 = w3[j];
            a0 += x0.x * y.x + x0.y * y.y + x0.z * y.z + x0.w * y.w;
            a1 += x1.x * y.x + x1.y * y.y + x1.z * y.z + x1.w * y.w;
            a2 += x2.x * y.x + x2.y * y.y + x2.z * y.z + x2.w * y.w;
            a3 += x3.x * y.x + x3.y * y.y + x3.z * y.z + x3.w * y.w;
        }
        #pragma unroll
        for (int o = 16; o > 0; o >>= 1) {
            a0 += __shfl_down_sync(0xffffffffu, a0, o);
            a1 += __shfl_down_sync(0xffffffffu, a1, o);
            a2 += __shfl_down_sync(0xffffffffu, a2, o);
            a3 += __shfl_down_sync(0xffffffffu, a3, o);
        }
        if (lane == 0) {
            q_sm[warp * 4 + 0] = a0 + q_b[e0 + 0];
            q_sm[warp * 4 + 1] = a1 + q_b[e0 + 1];
            q_sm[warp * 4 + 2] = a2 + q_b[e0 + 2];
            q_sm[warp * 4 + 3] = a3 + q_b[e0 + 3];
        }
    }
    __syncthreads();

    // qkb partial: one warp reduces this slice's 32 products
    if (warp == 0) {
        float p = q_sm[lane] * k_b[eBase + lane];
        #pragma unroll
        for (int o = 16; o > 0; o >>= 1) p += __shfl_xor_sync(0xffffffffu, p, o);
        if (lane == 0) atomicAdd(&g_qkb[b], SCALE * p);
    }

    // a[b,c] partial over this slice's 32 e-rows (k_w rows L2-hot across b)
    {
        int c0 = tid, c1 = tid + 256;       // c1 valid iff tid < 192
        float acc0 = 0.f, acc1 = 0.f;
        if (tid < 192) {
            #pragma unroll
            for (int j = 0; j < 32; ++j) {
                float qv = q_sm[j];
                const float* row = k_w + (size_t)(eBase + j) * C_;
                acc0 += qv * row[c0];
                acc1 += qv * row[c1];
            }
            atomicAdd(&g_a[b * C_ + c1], SCALE * acc1);
        } else {
            #pragma unroll
            for (int j = 0; j < 32; ++j)
                acc0 += q_sm[j] * k_w[(size_t)(eBase + j) * C_ + c0];
        }
        atomicAdd(&g_a[b * C_ + c0], SCALE * acc0);
    }
}

// ============================================================
// Kernel 2: all-register attention pass + fused pooled epilogue.
// One 16-pixel chunk per block; the block that draws the last
// ticket for its batch computes pooled[b,:] (g_S complete).
// ============================================================
__global__ void __launch_bounds__(256) k_attn_pass(
    const float* __restrict__ img,
    const float* __restrict__ v_w, const float* __restrict__ v_b)
{
    int gx = blockIdx.x, b = blockIdx.y;
    int tid = threadIdx.x;
    int warp = tid >> 5, lane = tid & 31;
    int v = tid & 3, k = tid >> 2;

    __shared__ float a_sm[C_];
    __shared__ float red_s[128];        // [warp][16] partial logits
    __shared__ float e_sm[CHUNK];
    __shared__ unsigned int last_sm;

    for (int c = tid; c < C_; c += 256) a_sm[c] = g_a[b * C_ + c];
    float qkb = g_qkb[b];

    // issue image loads immediately (independent of a_sm)
    const float* base = img + ((size_t)b * C_ + k) * N_ + gx * CHUNK + v * 4;
    float4 r[7];
    #pragma unroll
    for (int it = 0; it < 7; ++it)
        r[it] = __ldcs(reinterpret_cast<const float4*>(base + (size_t)(it * 64) * N_));
    __syncthreads();

    // per-thread a values for its 7 channels
    float aq[7];
    #pragma unroll
    for (int it = 0; it < 7; ++it) aq[it] = a_sm[it * 64 + k];

    // ---- phase A partials from registers (28 FMA) ----
    float plx = 0.f, ply = 0.f, plz = 0.f, plw = 0.f;
    #pragma unroll
    for (int it = 0; it < 7; ++it) {
        float a = aq[it];
        plx += a * r[it].x; ply += a * r[it].y;
        plz += a * r[it].z; plw += a * r[it].w;
    }

    // ---- reduce partials over lanes sharing v (strides 4,8,16) ----
    #pragma unroll
    for (int m = 4; m <= 16; m <<= 1) {
        plx += __shfl_xor_sync(0xffffffffu, plx, m);
        ply += __shfl_xor_sync(0xffffffffu, ply, m);
        plz += __shfl_xor_sync(0xffffffffu, plz, m);
        plw += __shfl_xor_sync(0xffffffffu, plw, m);
    }
    if (lane < 4) {      // lane == v for lanes 0..3
        float4 p4 = make_float4(plx, ply, plz, plw);
        reinterpret_cast<float4*>(red_s)[warp * 4 + lane] = p4;
    }
    __syncthreads();

    // ---- exp over 16 pixels + D flush ----
    if (tid < 16) {
        float lg = 0.f;
        #pragma unroll
        for (int w = 0; w < 8; ++w) lg += red_s[w * 16 + tid];
        float e = __expf(lg + qkb);
        e_sm[tid] = e;
        float d = e;
        d += __shfl_xor_sync(0xffffu, d, 8);
        d += __shfl_xor_sync(0xffffu, d, 4);
        d += __shfl_xor_sync(0xffffu, d, 2);
        d += __shfl_xor_sync(0xffffu, d, 1);
        if (tid == 0) atomicAdd(&g_D[b], d);
    }
    __syncthreads();

    // ---- phase B from registers (28 FMA) + flush ----
    float4 e4 = reinterpret_cast<const float4*>(e_sm)[v];
    #pragma unroll
    for (int it = 0; it < 7; ++it) {
        float s = r[it].x * e4.x + r[it].y * e4.y
                + r[it].z * e4.z + r[it].w * e4.w;
        s += __shfl_xor_sync(0xffffffffu, s, 1);
        s += __shfl_xor_sync(0xffffffffu, s, 2);
        if (v == 0) atomicAdd(&g_S[b * C_ + it * 64 + k], s);
    }

    // ---- ticket: last block for this b computes pooled[b,:] ----
    __threadfence();
    __syncthreads();
    if (tid == 0) last_sm = atomicAdd(&g_cnt[b], 1u);
    __syncthreads();
    if (last_sm != GX - 1) return;

    // this block: g_S[b]/g_D[b] are complete. Reuse a_sm for s.
    if (tid == 0) g_cnt[b] = 0;     // reset for next replay
    a_sm[tid] = g_S[b * C_ + tid];
    if (tid < C_ - 256) a_sm[tid + 256] = g_S[b * C_ + tid + 256];
    __syncthreads();
    float invD = 1.0f / g_D[b];

    // pooled: 8 trips, warp-per-4e, lanes coalesced over c
    for (int rr = 0; rr < 32; rr += 4) {
        int e0 = warp * 32 + rr;
        const float* w0 = v_w + (size_t)(e0 + 0) * C_;
        const float* w1 = v_w + (size_t)(e0 + 1) * C_;
        const float* w2 = v_w + (size_t)(e0 + 2) * C_;
        const float* w3 = v_w + (size_t)(e0 + 3) * C_;
        float acc0 = 0.f, acc1 = 0.f, acc2 = 0.f, acc3 = 0.f;
        #pragma unroll
        for (int it = 0; it < 14; ++it) {
            int c = it * 32 + lane;
            float sv = a_sm[c];
            acc0 += w0[c] * sv;
            acc1 += w1[c] * sv;
            acc2 += w2[c] * sv;
            acc3 += w3[c] * sv;
        }
        #pragma unroll
        for (int o = 16; o > 0; o >>= 1) {
            acc0 += __shfl_down_sync(0xffffffffu, acc0, o);
            acc1 += __shfl_down_sync(0xffffffffu, acc1, o);
            acc2 += __shfl_down_sync(0xffffffffu, acc2, o);
            acc3 += __shfl_down_sync(0xffffffffu, acc3, o);
        }
        if (lane == 0) {
            g_pooled[b * E_ + e0 + 0] = acc0 * invD + v_b[e0 + 0];
            g_pooled[b * E_ + e0 + 1] = acc1 * invD + v_b[e0 + 1];
            g_pooled[b * E_ + e0 + 2] = acc2 * invD + v_b[e0 + 2];
            g_pooled[b * E_ + e0 + 3] = acc3 * invD + v_b[e0 + 3];
        }
    }
}

// ============================================================
// Kernel 3: fused out-projection + residual. Barrier-free,
// streaming loads/stores. Tail: re-zero accumulators for the
// next graph replay (grid == B_*C_ covers every element).
// ============================================================
__global__ void __launch_bounds__(256) k_residual(const float* __restrict__ img,
                                                  const float* __restrict__ o_w,
                                                  const float* __restrict__ o_b,
                                                  float* __restrict__ out)
{
    int blk = blockIdx.x;              // 0 .. B_*C_-1
    int b = blk / C_, c = blk - b * C_;
    int tid = threadIdx.x, lane = tid & 31;

    const float4* src = reinterpret_cast<const float4*>(img) + (size_t)blk * (N_ / 4);
    float4* dst = reinterpret_cast<float4*>(out) + (size_t)blk * (N_ / 4);

    // issue image loads first (784 float4: 3 per thread + 16-thread tail)
    float4 r0 = __ldcs(src + tid);
    float4 r1 = __ldcs(src + tid + 256);
    float4 r2 = __ldcs(src + tid + 512);
    float4 r3;
    if (tid < 16) r3 = __ldcs(src + tid + 768);

    // per-warp dot over e (o_w row + pooled row are cache-hot)
    const float* wr = o_w + (size_t)c * E_;
    const float* pl = g_pooled + b * E_;
    float p = 0.f;
    #pragma unroll
    for (int it = 0; it < 8; ++it) {
        int e = it * 32 + lane;
        p += wr[e] * pl[e];
    }
    #pragma unroll
    for (int o = 16; o > 0; o >>= 1) p += __shfl_xor_sync(0xffffffffu, p, o);
    float add = p + __ldg(&o_b[c]);

    // re-zero accumulators for the next replay (one element per block)
    if (tid == 64) {
        g_a[blk] = 0.f;
        g_S[blk] = 0.f;
        if (blk < B_) { g_qkb[blk] = 0.f; g_D[blk] = 0.f; }
    }

    r0.x += add; r0.y += add; r0.z += add; r0.w += add;
    r1.x += add; r1.y += add; r1.z += add; r1.w += add;
    r2.x += add; r2.y += add; r2.z += add; r2.w += add;
    __stcs(dst + tid, r0);
    __stcs(dst + tid + 256, r1);
    __stcs(dst + tid + 512, r2);
    if (tid < 16) {
        r3.x += add; r3.y += add; r3.z += add; r3.w += add;
        __stcs(dst + tid + 768, r3);
    }
}

// ============================================================
extern "C" void kernel_launch(void* const* d_in, const int* in_sizes, int n_in,
                              void* d_out, int out_size)
{
    const float* text = (const float*)d_in[0];
    const float* img  = (const float*)d_in[1];
    const float* q_w  = (const float*)d_in[2];
    const float* q_b  = (const float*)d_in[3];
    const float* k_w  = (const float*)d_in[4];
    const float* k_b  = (const float*)d_in[5];
    const float* v_w  = (const float*)d_in[6];
    const float* v_b  = (const float*)d_in[7];
    const float* o_w  = (const float*)d_in[8];
    const float* o_b  = (const float*)d_in[9];
    float* out = (float*)d_out;

    k_qa<<<dim3(8, B_), 256>>>(text, q_w, q_b, k_w, k_b);
    k_attn_pass<<<dim3(GX, B_), 256>>>(img, v_w, v_b);
    k_residual<<<B_ * C_, 256>>>(img, o_w, o_b, out);
}

// round 11
// speedup vs baseline: 1.1539x; 1.1539x over previous
#include <cuda_runtime.h>
#include <cuda_bf16.h>
#include <cstdint>

// Problem shape (fixed by the dataset)
#define B_  32
#define T_  768
#define C_  448
#define E_  256
#define N_  3136          // H*W = 56*56
#define SCALE 0.0625f     // 1/sqrt(E)

#define CHUNK 16
#define GX 196                // pixel-groups per batch: 196*16 = 3136 exact

// -------- device scratch (no allocations allowed) --------
// Zero-initialized statics; re-zeroed at the tail of k_residual so every
// graph replay sees clean state.
__device__ float g_a[B_ * C_];       // scale * (q[b]^T k_w)[c]   (atomic acc)
__device__ float g_qkb[B_];          // scale * q[b].k_b          (atomic acc)
__device__ float g_S[B_ * C_];       // attention-weighted channel sums (atomic)
__device__ float g_D[B_];            // exp-sum (atomic)
__device__ float g_pooled[B_ * E_];  // pooled (already /D, +v_b)

// ============================================================
// Kernel 1: fused q-projection + a-projection, wide version.
// grid (32, B_): block computes q[e] for its 8-e slice
// (warp-per-e, one load batch), then contributes partial
// a[b,c] (8 rows) and qkb[b] via atomicAdd.
// ============================================================
__global__ void __launch_bounds__(256) k_qa(
    const float* __restrict__ text, const float* __restrict__ q_w,
    const float* __restrict__ q_b,  const float* __restrict__ k_w,
    const float* __restrict__ k_b)
{
    int slice = blockIdx.x, b = blockIdx.y;
    int tid = threadIdx.x, warp = tid >> 5, lane = tid & 31;
    __shared__ float txt[T_];
    __shared__ float q_sm[8];

    if (tid < T_ / 4)    // 192 float4s
        reinterpret_cast<float4*>(txt)[tid] =
            reinterpret_cast<const float4*>(text + (size_t)b * T_)[tid];
    __syncthreads();

    int eBase = slice * 8;
    // warp-per-e q dot: single 6-load batch + one shuffle chain
    {
        int e = eBase + warp;
        const float4* w = reinterpret_cast<const float4*>(q_w + (size_t)e * T_);
        const float4* tt = reinterpret_cast<const float4*>(txt);
        float acc = 0.f;
        #pragma unroll
        for (int it = 0; it < 6; ++it) {          // 6*32*4 = 768 exact
            int j = it * 32 + lane;
            float4 x = w[j], y = tt[j];
            acc += x.x * y.x + x.y * y.y + x.z * y.z + x.w * y.w;
        }
        #pragma unroll
        for (int o = 16; o > 0; o >>= 1) acc += __shfl_down_sync(0xffffffffu, acc, o);
        if (lane == 0) q_sm[warp] = acc + q_b[e];
    }
    __syncthreads();

    // qkb partial: 8 products, reduced in warp 0
    if (warp == 0) {
        float p = (lane < 8) ? q_sm[lane] * k_b[eBase + lane] : 0.f;
        p += __shfl_xor_sync(0xffffffffu, p, 4);
        p += __shfl_xor_sync(0xffffffffu, p, 2);
        p += __shfl_xor_sync(0xffffffffu, p, 1);
        if (lane == 0) atomicAdd(&g_qkb[b], SCALE * p);
    }

    // a[b,c] partial over this slice's 8 e-rows (k_w rows L2-hot across b)
    {
        int c0 = tid, c1 = tid + 256;       // c1 valid iff tid < 192
        float acc0 = 0.f, acc1 = 0.f;
        if (tid < 192) {
            #pragma unroll
            for (int j = 0; j < 8; ++j) {
                float qv = q_sm[j];
                const float* row = k_w + (size_t)(eBase + j) * C_;
                acc0 += qv * row[c0];
                acc1 += qv * row[c1];
            }
            atomicAdd(&g_a[b * C_ + c1], SCALE * acc1);
        } else {
            #pragma unroll
            for (int j = 0; j < 8; ++j)
                acc0 += q_sm[j] * k_w[(size_t)(eBase + j) * C_ + c0];
        }
        atomicAdd(&g_a[b * C_ + c0], SCALE * acc0);
    }
}

// ============================================================
// Kernel 2: all-register attention pass, one 16-pixel chunk per
// block. Thread layout: v = tid&3 (pixel quarter), k = tid>>2;
// thread owns channels it*64+k (it=0..6), pixels v*4..v*4+3.
// ============================================================
__global__ void __launch_bounds__(256) k_attn_pass(const float* __restrict__ img)
{
    int gx = blockIdx.x, b = blockIdx.y;
    int tid = threadIdx.x;
    int warp = tid >> 5, lane = tid & 31;
    int v = tid & 3, k = tid >> 2;

    __shared__ float a_sm[C_];
    __shared__ float red_s[128];        // [warp][16] partial logits
    __shared__ float e_sm[CHUNK];

    for (int c = tid; c < C_; c += 256) a_sm[c] = g_a[b * C_ + c];
    float qkb = g_qkb[b];

    // issue image loads immediately (independent of a_sm)
    const float* base = img + ((size_t)b * C_ + k) * N_ + gx * CHUNK + v * 4;
    float4 r[7];
    #pragma unroll
    for (int it = 0; it < 7; ++it)
        r[it] = __ldcs(reinterpret_cast<const float4*>(base + (size_t)(it * 64) * N_));
    __syncthreads();

    // per-thread a values for its 7 channels
    float aq[7];
    #pragma unroll
    for (int it = 0; it < 7; ++it) aq[it] = a_sm[it * 64 + k];

    // ---- phase A partials from registers (28 FMA) ----
    float plx = 0.f, ply = 0.f, plz = 0.f, plw = 0.f;
    #pragma unroll
    for (int it = 0; it < 7; ++it) {
        float a = aq[it];
        plx += a * r[it].x; ply += a * r[it].y;
        plz += a * r[it].z; plw += a * r[it].w;
    }

    // ---- reduce partials over lanes sharing v (strides 4,8,16) ----
    #pragma unroll
    for (int m = 4; m <= 16; m <<= 1) {
        plx += __shfl_xor_sync(0xffffffffu, plx, m);
        ply += __shfl_xor_sync(0xffffffffu, ply, m);
        plz += __shfl_xor_sync(0xffffffffu, plz, m);
        plw += __shfl_xor_sync(0xffffffffu, plw, m);
    }
    if (lane < 4) {      // lane == v for lanes 0..3
        float4 p4 = make_float4(plx, ply, plz, plw);
        reinterpret_cast<float4*>(red_s)[warp * 4 + lane] = p4;
    }
    __syncthreads();

    // ---- exp over 16 pixels + D flush ----
    if (tid < 16) {
        float lg = 0.f;
        #pragma unroll
        for (int w = 0; w < 8; ++w) lg += red_s[w * 16 + tid];
        float e = __expf(lg + qkb);
        e_sm[tid] = e;
        float d = e;
        d += __shfl_xor_sync(0xffffu, d, 8);
        d += __shfl_xor_sync(0xffffu, d, 4);
        d += __shfl_xor_sync(0xffffu, d, 2);
        d += __shfl_xor_sync(0xffffu, d, 1);
        if (tid == 0) atomicAdd(&g_D[b], d);
    }
    __syncthreads();

    // ---- phase B from registers (28 FMA) + flush ----
    float4 e4 = reinterpret_cast<const float4*>(e_sm)[v];
    #pragma unroll
    for (int it = 0; it < 7; ++it) {
        float s = r[it].x * e4.x + r[it].y * e4.y
                + r[it].z * e4.z + r[it].w * e4.w;
        s += __shfl_xor_sync(0xffffffffu, s, 1);
        s += __shfl_xor_sync(0xffffffffu, s, 2);
        if (v == 0) atomicAdd(&g_S[b * C_ + it * 64 + k], s);
    }
}

// ============================================================
// Kernel 3: pooled = v_w @ (g_S/D) + v_b.
// grid (B_, 8): warp-per-4e, one trip; g_S is tiny & L2-hot.
// ============================================================
__global__ void __launch_bounds__(256) k_pool(
    const float* __restrict__ v_w, const float* __restrict__ v_b)
{
    int b = blockIdx.x, slice = blockIdx.y;
    int tid = threadIdx.x, warp = tid >> 5, lane = tid & 31;
    __shared__ float s_sm[C_];
    __shared__ float invD_sm;

    s_sm[tid] = g_S[b * C_ + tid];
    if (tid < C_ - 256) s_sm[tid + 256] = g_S[b * C_ + tid + 256];
    if (tid == 0) invD_sm = 1.0f / g_D[b];
    __syncthreads();
    float invD = invD_sm;

    int e0 = slice * 32 + warp * 4;
    const float* w0 = v_w + (size_t)(e0 + 0) * C_;
    const float* w1 = v_w + (size_t)(e0 + 1) * C_;
    const float* w2 = v_w + (size_t)(e0 + 2) * C_;
    const float* w3 = v_w + (size_t)(e0 + 3) * C_;
    float acc0 = 0.f, acc1 = 0.f, acc2 = 0.f, acc3 = 0.f;
    #pragma unroll
    for (int it = 0; it < 14; ++it) {
        int c = it * 32 + lane;
        float sv = s_sm[c];
        acc0 += w0[c] * sv;
        acc1 += w1[c] * sv;
        acc2 += w2[c] * sv;
        acc3 += w3[c] * sv;
    }
    #pragma unroll
    for (int o = 16; o > 0; o >>= 1) {
        acc0 += __shfl_down_sync(0xffffffffu, acc0, o);
        acc1 += __shfl_down_sync(0xffffffffu, acc1, o);
        acc2 += __shfl_down_sync(0xffffffffu, acc2, o);
        acc3 += __shfl_down_sync(0xffffffffu, acc3, o);
    }
    if (lane == 0) {
        g_pooled[b * E_ + e0 + 0] = acc0 * invD + v_b[e0 + 0];
        g_pooled[b * E_ + e0 + 1] = acc1 * invD + v_b[e0 + 1];
        g_pooled[b * E_ + e0 + 2] = acc2 * invD + v_b[e0 + 2];
        g_pooled[b * E_ + e0 + 3] = acc3 * invD + v_b[e0 + 3];
    }
}

// ============================================================
// Kernel 4: fused out-projection + residual. Barrier-free,
// streaming loads/stores. Tail: re-zero accumulators for the
// next graph replay (grid == B_*C_ covers every element).
// ============================================================
__global__ void __launch_bounds__(256) k_residual(const float* __restrict__ img,
                                                  const float* __restrict__ o_w,
                                                  const float* __restrict__ o_b,
                                                  float* __restrict__ out)
{
    int blk = blockIdx.x;              // 0 .. B_*C_-1
    int b = blk / C_, c = blk - b * C_;
    int tid = threadIdx.x, lane = tid & 31;

    const float4* src = reinterpret_cast<const float4*>(img) + (size_t)blk * (N_ / 4);
    float4* dst = reinterpret_cast<float4*>(out) + (size_t)blk * (N_ / 4);

    // issue image loads first (784 float4: 3 per thread + 16-thread tail)
    float4 r0 = __ldcs(src + tid);
    float4 r1 = __ldcs(src + tid + 256);
    float4 r2 = __ldcs(src + tid + 512);
    float4 r3;
    if (tid < 16) r3 = __ldcs(src + tid + 768);

    // per-warp dot over e (o_w row + pooled row are cache-hot)
    const float* wr = o_w + (size_t)c * E_;
    const float* pl = g_pooled + b * E_;
    float p = 0.f;
    #pragma unroll
    for (int it = 0; it < 8; ++it) {
        int e = it * 32 + lane;
        p += wr[e] * pl[e];
    }
    #pragma unroll
    for (int o = 16; o > 0; o >>= 1) p += __shfl_xor_sync(0xffffffffu, p, o);
    float add = p + __ldg(&o_b[c]);

    // re-zero accumulators for the next replay (one element per block)
    if (tid == 64) {
        g_a[blk] = 0.f;
        g_S[blk] = 0.f;
        if (blk < B_) { g_qkb[blk] = 0.f; g_D[blk] = 0.f; }
    }

    r0.x += add; r0.y += add; r0.z += add; r0.w += add;
    r1.x += add; r1.y += add; r1.z += add; r1.w += add;
    r2.x += add; r2.y += add; r2.z += add; r2.w += add;
    __stcs(dst + tid, r0);
    __stcs(dst + tid + 256, r1);
    __stcs(dst + tid + 512, r2);
    if (tid < 16) {
        r3.x += add; r3.y += add; r3.z += add; r3.w += add;
        __stcs(dst + tid + 768, r3);
    }
}

// ============================================================
extern "C" void kernel_launch(void* const* d_in, const int* in_sizes, int n_in,
                              void* d_out, int out_size)
{
    const float* text = (const float*)d_in[0];
    const float* img  = (const float*)d_in[1];
    const float* q_w  = (const float*)d_in[2];
    const float* q_b  = (const float*)d_in[3];
    const float* k_w  = (const float*)d_in[4];
    const float* k_b  = (const float*)d_in[5];
    const float* v_w  = (const float*)d_in[6];
    const float* v_b  = (const float*)d_in[7];
    const float* o_w  = (const float*)d_in[8];
    const float* o_b  = (const float*)d_in[9];
    float* out = (float*)d_out;

    k_qa<<<dim3(32, B_), 256>>>(text, q_w, q_b, k_w, k_b);
    k_attn_pass<<<dim3(GX, B_), 256>>>(img);
    k_pool<<<dim3(B_, 8), 256>>>(v_w, v_b);
    k_residual<<<B_ * C_, 256>>>(img, o_w, o_b, out);
}

// round 12
// speedup vs baseline: 1.1751x; 1.0184x over previous
#include <cuda_runtime.h>
#include <cuda_bf16.h>
#include <cstdint>

// Problem shape (fixed by the dataset)
#define B_  32
#define T_  768
#define C_  448
#define E_  256
#define N_  3136          // H*W = 56*56
#define SCALE 0.0625f     // 1/sqrt(E)

#define CHUNK 16
#define GX 196                // pixel-groups per batch: 196*16 = 3136 exact

// -------- device scratch (no allocations allowed) --------
// Zero-initialized statics; re-zeroed at the tail of k_residual so every
// graph replay sees clean state.
__device__ float g_a[B_ * C_];       // scale * (q[b]^T k_w)[c]   (atomic acc)
__device__ float g_qkb[B_];          // scale * q[b].k_b          (atomic acc)
__device__ float g_S[B_ * C_];       // attention-weighted channel sums (atomic)
__device__ float g_D[B_];            // exp-sum (atomic)
__device__ float g_pooled[B_ * E_];  // pooled (already /D, +v_b)

// ============================================================
// Kernel 1: fused q-projection + a-projection, wide version.
// grid (32, B_): block computes q[e] for its 8-e slice
// (warp-per-e, one load batch), then contributes partial
// a[b,c] (8 rows) and qkb[b] via atomicAdd.
// ============================================================
__global__ void __launch_bounds__(256) k_qa(
    const float* __restrict__ text, const float* __restrict__ q_w,
    const float* __restrict__ q_b,  const float* __restrict__ k_w,
    const float* __restrict__ k_b)
{
    int slice = blockIdx.x, b = blockIdx.y;
    int tid = threadIdx.x, warp = tid >> 5, lane = tid & 31;
    __shared__ float txt[T_];
    __shared__ float q_sm[8];

    if (tid < T_ / 4)    // 192 float4s
        reinterpret_cast<float4*>(txt)[tid] =
            reinterpret_cast<const float4*>(text + (size_t)b * T_)[tid];
    __syncthreads();

    int eBase = slice * 8;
    // warp-per-e q dot: single 6-load batch + one shuffle chain
    {
        int e = eBase + warp;
        const float4* w = reinterpret_cast<const float4*>(q_w + (size_t)e * T_);
        const float4* tt = reinterpret_cast<const float4*>(txt);
        float acc = 0.f;
        #pragma unroll
        for (int it = 0; it < 6; ++it) {          // 6*32*4 = 768 exact
            int j = it * 32 + lane;
            float4 x = w[j], y = tt[j];
            acc += x.x * y.x + x.y * y.y + x.z * y.z + x.w * y.w;
        }
        #pragma unroll
        for (int o = 16; o > 0; o >>= 1) acc += __shfl_down_sync(0xffffffffu, acc, o);
        if (lane == 0) q_sm[warp] = acc + q_b[e];
    }
    __syncthreads();

    // qkb partial: 8 products, reduced in warp 0
    if (warp == 0) {
        float p = (lane < 8) ? q_sm[lane] * k_b[eBase + lane] : 0.f;
        p += __shfl_xor_sync(0xffffffffu, p, 4);
        p += __shfl_xor_sync(0xffffffffu, p, 2);
        p += __shfl_xor_sync(0xffffffffu, p, 1);
        if (lane == 0) atomicAdd(&g_qkb[b], SCALE * p);
    }

    // a[b,c] partial over this slice's 8 e-rows (k_w rows L2-hot across b)
    {
        int c0 = tid, c1 = tid + 256;       // c1 valid iff tid < 192
        float acc0 = 0.f, acc1 = 0.f;
        if (tid < 192) {
            #pragma unroll
            for (int j = 0; j < 8; ++j) {
                float qv = q_sm[j];
                const float* row = k_w + (size_t)(eBase + j) * C_;
                acc0 += qv * row[c0];
                acc1 += qv * row[c1];
            }
            atomicAdd(&g_a[b * C_ + c1], SCALE * acc1);
        } else {
            #pragma unroll
            for (int j = 0; j < 8; ++j)
                acc0 += q_sm[j] * k_w[(size_t)(eBase + j) * C_ + c0];
        }
        atomicAdd(&g_a[b * C_ + c0], SCALE * acc0);
    }
}

// ============================================================
// Kernel 2: all-register attention pass, one 16-pixel chunk per
// block. Plain (caching) img loads: they populate L2 so the
// residual pass can re-read the tail of img from L2, not DRAM.
// ============================================================
__global__ void __launch_bounds__(256) k_attn_pass(const float* __restrict__ img)
{
    int gx = blockIdx.x, b = blockIdx.y;
    int tid = threadIdx.x;
    int warp = tid >> 5, lane = tid & 31;
    int v = tid & 3, k = tid >> 2;

    __shared__ float a_sm[C_];
    __shared__ float red_s[128];        // [warp][16] partial logits
    __shared__ float e_sm[CHUNK];

    for (int c = tid; c < C_; c += 256) a_sm[c] = g_a[b * C_ + c];
    float qkb = g_qkb[b];

    // issue image loads immediately (independent of a_sm)
    const float* base = img + ((size_t)b * C_ + k) * N_ + gx * CHUNK + v * 4;
    float4 r[7];
    #pragma unroll
    for (int it = 0; it < 7; ++it)
        r[it] = *reinterpret_cast<const float4*>(base + (size_t)(it * 64) * N_);
    __syncthreads();

    // per-thread a values for its 7 channels
    float aq[7];
    #pragma unroll
    for (int it = 0; it < 7; ++it) aq[it] = a_sm[it * 64 + k];

    // ---- phase A partials from registers (28 FMA) ----
    float plx = 0.f, ply = 0.f, plz = 0.f, plw = 0.f;
    #pragma unroll
    for (int it = 0; it < 7; ++it) {
        float a = aq[it];
        plx += a * r[it].x; ply += a * r[it].y;
        plz += a * r[it].z; plw += a * r[it].w;
    }

    // ---- reduce partials over lanes sharing v (strides 4,8,16) ----
    #pragma unroll
    for (int m = 4; m <= 16; m <<= 1) {
        plx += __shfl_xor_sync(0xffffffffu, plx, m);
        ply += __shfl_xor_sync(0xffffffffu, ply, m);
        plz += __shfl_xor_sync(0xffffffffu, plz, m);
        plw += __shfl_xor_sync(0xffffffffu, plw, m);
    }
    if (lane < 4) {      // lane == v for lanes 0..3
        float4 p4 = make_float4(plx, ply, plz, plw);
        reinterpret_cast<float4*>(red_s)[warp * 4 + lane] = p4;
    }
    __syncthreads();

    // ---- exp over 16 pixels + D flush ----
    if (tid < 16) {
        float lg = 0.f;
        #pragma unroll
        for (int w = 0; w < 8; ++w) lg += red_s[w * 16 + tid];
        float e = __expf(lg + qkb);
        e_sm[tid] = e;
        float d = e;
        d += __shfl_xor_sync(0xffffu, d, 8);
        d += __shfl_xor_sync(0xffffu, d, 4);
        d += __shfl_xor_sync(0xffffu, d, 2);
        d += __shfl_xor_sync(0xffffu, d, 1);
        if (tid == 0) atomicAdd(&g_D[b], d);
    }
    __syncthreads();

    // ---- phase B from registers (28 FMA) + flush ----
    float4 e4 = reinterpret_cast<const float4*>(e_sm)[v];
    #pragma unroll
    for (int it = 0; it < 7; ++it) {
        float s = r[it].x * e4.x + r[it].y * e4.y
                + r[it].z * e4.z + r[it].w * e4.w;
        s += __shfl_xor_sync(0xffffffffu, s, 1);
        s += __shfl_xor_sync(0xffffffffu, s, 2);
        if (v == 0) atomicAdd(&g_S[b * C_ + it * 64 + k], s);
    }
}

// ============================================================
// Kernel 3: pooled = v_w @ (g_S/D) + v_b.
// grid (B_, 8): warp-per-4e, one trip; g_S is tiny & L2-hot.
// ============================================================
__global__ void __launch_bounds__(256) k_pool(
    const float* __restrict__ v_w, const float* __restrict__ v_b)
{
    int b = blockIdx.x, slice = blockIdx.y;
    int tid = threadIdx.x, warp = tid >> 5, lane = tid & 31;
    __shared__ float s_sm[C_];
    __shared__ float invD_sm;

    s_sm[tid] = g_S[b * C_ + tid];
    if (tid < C_ - 256) s_sm[tid + 256] = g_S[b * C_ + tid + 256];
    if (tid == 0) invD_sm = 1.0f / g_D[b];
    __syncthreads();
    float invD = invD_sm;

    int e0 = slice * 32 + warp * 4;
    const float* w0 = v_w + (size_t)(e0 + 0) * C_;
    const float* w1 = v_w + (size_t)(e0 + 1) * C_;
    const float* w2 = v_w + (size_t)(e0 + 2) * C_;
    const float* w3 = v_w + (size_t)(e0 + 3) * C_;
    float acc0 = 0.f, acc1 = 0.f, acc2 = 0.f, acc3 = 0.f;
    #pragma unroll
    for (int it = 0; it < 14; ++it) {
        int c = it * 32 + lane;
        float sv = s_sm[c];
        acc0 += w0[c] * sv;
        acc1 += w1[c] * sv;
        acc2 += w2[c] * sv;
        acc3 += w3[c] * sv;
    }
    #pragma unroll
    for (int o = 16; o > 0; o >>= 1) {
        acc0 += __shfl_down_sync(0xffffffffu, acc0, o);
        acc1 += __shfl_down_sync(0xffffffffu, acc1, o);
        acc2 += __shfl_down_sync(0xffffffffu, acc2, o);
        acc3 += __shfl_down_sync(0xffffffffu, acc3, o);
    }
    if (lane == 0) {
        g_pooled[b * E_ + e0 + 0] = acc0 * invD + v_b[e0 + 0];
        g_pooled[b * E_ + e0 + 1] = acc1 * invD + v_b[e0 + 1];
        g_pooled[b * E_ + e0 + 2] = acc2 * invD + v_b[e0 + 2];
        g_pooled[b * E_ + e0 + 3] = acc3 * invD + v_b[e0 + 3];
    }
}

// ============================================================
// Kernel 4: fused out-projection + residual. REVERSED block
// order: reads batch 31 first — the region the attn pass read
// last and which is therefore still L2-resident. Plain img
// loads (may hit L2); .cs stores so the write stream doesn't
// evict the reusable img data. Tail: re-zero accumulators.
// ============================================================
__global__ void __launch_bounds__(256) k_residual(const float* __restrict__ img,
                                                  const float* __restrict__ o_w,
                                                  const float* __restrict__ o_b,
                                                  float* __restrict__ out)
{
    int blk = (B_ * C_ - 1) - blockIdx.x;   // reversed: batch 31 first
    int b = blk / C_, c = blk - b * C_;
    int tid = threadIdx.x, lane = tid & 31;

    const float4* src = reinterpret_cast<const float4*>(img) + (size_t)blk * (N_ / 4);
    float4* dst = reinterpret_cast<float4*>(out) + (size_t)blk * (N_ / 4);

    // issue image loads first (784 float4: 3 per thread + 16-thread tail)
    float4 r0 = src[tid];
    float4 r1 = src[tid + 256];
    float4 r2 = src[tid + 512];
    float4 r3;
    if (tid < 16) r3 = src[tid + 768];

    // per-warp dot over e (o_w row + pooled row are cache-hot)
    const float* wr = o_w + (size_t)c * E_;
    const float* pl = g_pooled + b * E_;
    float p = 0.f;
    #pragma unroll
    for (int it = 0; it < 8; ++it) {
        int e = it * 32 + lane;
        p += wr[e] * pl[e];
    }
    #pragma unroll
    for (int o = 16; o > 0; o >>= 1) p += __shfl_xor_sync(0xffffffffu, p, o);
    float add = p + __ldg(&o_b[c]);

    // re-zero accumulators for the next replay (one element per block)
    if (tid == 64) {
        g_a[blk] = 0.f;
        g_S[blk] = 0.f;
        if (blk < B_) { g_qkb[blk] = 0.f; g_D[blk] = 0.f; }
    }

    r0.x += add; r0.y += add; r0.z += add; r0.w += add;
    r1.x += add; r1.y += add; r1.z += add; r1.w += add;
    r2.x += add; r2.y += add; r2.z += add; r2.w += add;
    __stcs(dst + tid, r0);
    __stcs(dst + tid + 256, r1);
    __stcs(dst + tid + 512, r2);
    if (tid < 16) {
        r3.x += add; r3.y += add; r3.z += add; r3.w += add;
        __stcs(dst + tid + 768, r3);
    }
}

// ============================================================
extern "C" void kernel_launch(void* const* d_in, const int* in_sizes, int n_in,
                              void* d_out, int out_size)
{
    const float* text = (const float*)d_in[0];
    const float* img  = (const float*)d_in[1];
    const float* q_w  = (const float*)d_in[2];
    const float* q_b  = (const float*)d_in[3];
    const float* k_w  = (const float*)d_in[4];
    const float* k_b  = (const float*)d_in[5];
    const float* v_w  = (const float*)d_in[6];
    const float* v_b  = (const float*)d_in[7];
    const float* o_w  = (const float*)d_in[8];
    const float* o_b  = (const float*)d_in[9];
    float* out = (float*)d_out;

    k_qa<<<dim3(32, B_), 256>>>(text, q_w, q_b, k_w, k_b);
    k_attn_pass<<<dim3(GX, B_), 256>>>(img);
    k_pool<<<dim3(B_, 8), 256>>>(v_w, v_b);
    k_residual<<<B_ * C_, 256>>>(img, o_w, o_b, out);
}